// round 1
// baseline (speedup 1.0000x reference)
#include <cuda_runtime.h>
#include <cstdint>

// MvCnnDownLayer: out[b,h] = relu(conv1dW(in[b,h] + out[b,h-1]) + bias)
// B=16,H=256,W=256,C=32,K=5 (pad 2/2). Persistent kernel:
//  - 16 clusters (one per b) x 8 CTAs (32 W-positions each), 128 thr/CTA
//  - state X (row + carry) in SMEM, channel-major [c][36] with 2-halo, double buffered
//  - weights restaged in SMEM as [k][c][oc] for broadcast 128-bit loads
//  - per-row: f32x2 FMA conv -> relu+bias -> STG out -> build next X (+ DSMEM halo
//    to neighbor CTAs) -> barrier.cluster (release/acquire orders the halo stores)

#define Bn 16
#define Hn 256
#define Wn 256
#define Cn 32
#define Kn 5
#define XW 36   // 32 interior + 2 halo each side

__global__ void __cluster_dims__(8, 1, 1) __launch_bounds__(128)
mvcnn_down_kernel(const float* __restrict__ in, const float* __restrict__ wg,
                  const float* __restrict__ bias, float* __restrict__ out)
{
    __shared__ float Xs[2][Cn * XW];                 // [parity][c*36 + xi]
    __shared__ __align__(16) float Wsm[Kn * Cn * Cn]; // [(k*32+c)*32 + oc]

    const int tid  = threadIdx.x;
    const int x    = tid & 31;        // local W position within segment
    const int ocb  = (tid >> 5) * 8;  // output-channel base (warp-major)
    const int b    = blockIdx.x >> 3;
    const int rank = blockIdx.x & 7;
    const int seg  = rank * 32;
    const int gx   = seg + x;

    // --- stage weights: Wsm[(k*32+c)*32+oc] = w[(c*5+k)*32+oc] ---
    for (int i2 = tid; i2 < Kn * Cn * Cn; i2 += 128) {
        int oc = i2 & 31;
        int kc = i2 >> 5;
        int c  = kc & 31;
        int k  = kc >> 5;
        Wsm[i2] = wg[(c * Kn + k) * Cn + oc];
    }

    float bv[8];
#pragma unroll
    for (int j = 0; j < 8; ++j) bv[j] = bias[ocb + j];

    // --- zero halo columns (both parities, all channels) ---
    {
        int c  = tid & 31;
        int q  = tid >> 5;                 // 0..3
        int xi = (q < 2) ? q : q + 32;     // 0,1,34,35
        Xs[0][c * XW + xi] = 0.f;
        Xs[1][c * XW + xi] = 0.f;
    }
    __syncthreads();

    const float* inb  = in  + ((size_t)b * Hn * Wn + gx) * Cn;
    float*       outb = out + ((size_t)b * Hn * Wn + gx) * Cn;
    const size_t rstride = (size_t)Wn * Cn;

    // --- row 0 interior: X0 = input row 0 (carry = 0) ---
    {
        const float4* ip = (const float4*)(inb + ocb);
        float4 v0 = ip[0], v1 = ip[1];
        Xs[0][(ocb + 0) * XW + 2 + x] = v0.x;
        Xs[0][(ocb + 1) * XW + 2 + x] = v0.y;
        Xs[0][(ocb + 2) * XW + 2 + x] = v0.z;
        Xs[0][(ocb + 3) * XW + 2 + x] = v0.w;
        Xs[0][(ocb + 4) * XW + 2 + x] = v1.x;
        Xs[0][(ocb + 5) * XW + 2 + x] = v1.y;
        Xs[0][(ocb + 6) * XW + 2 + x] = v1.z;
        Xs[0][(ocb + 7) * XW + 2 + x] = v1.w;
    }
    // --- row 0 halo straight from global input ---
    if (tid < 16) {
        int hx = tid >> 2;                 // 0..3
        int og = (tid & 3) * 8;
        int xi = (hx < 2) ? hx : hx + 32;  // 0,1,34,35
        int g  = seg - 2 + xi;
        float v[8] = {0, 0, 0, 0, 0, 0, 0, 0};
        if (g >= 0 && g < Wn) {
            const float4* hp = (const float4*)(in + ((size_t)b * Hn * Wn + g) * Cn + og);
            float4 a = hp[0], c4 = hp[1];
            v[0] = a.x;  v[1] = a.y;  v[2] = a.z;  v[3] = a.w;
            v[4] = c4.x; v[5] = c4.y; v[6] = c4.z; v[7] = c4.w;
        }
#pragma unroll
        for (int j = 0; j < 8; ++j) Xs[0][(og + j) * XW + xi] = v[j];
    }
    __syncthreads();
    asm volatile("barrier.cluster.arrive.aligned;\n\tbarrier.cluster.wait.aligned;" ::: "memory");

    // --- neighbor SMEM base addresses for halo writes ---
    unsigned xs_base = (unsigned)__cvta_generic_to_shared(&Xs[0][0]);
    unsigned left_base = 0, right_base = 0;
    if (rank > 0)
        asm("mapa.shared::cluster.u32 %0, %1, %2;" : "=r"(left_base)  : "r"(xs_base), "r"(rank - 1));
    if (rank < 7)
        asm("mapa.shared::cluster.u32 %0, %1, %2;" : "=r"(right_base) : "r"(xs_base), "r"(rank + 1));

    for (int i = 0; i < Hn; ++i) {
        const int  p    = i & 1;
        const bool more = (i + 1 < Hn);

        // prefetch next input row (consumed ~1.5k cycles later in the epilogue)
        float4 pf0, pf1;
        pf0 = make_float4(0.f, 0.f, 0.f, 0.f);
        pf1 = pf0;
        if (more) {
            const float4* np = (const float4*)(inb + (size_t)(i + 1) * rstride + ocb);
            pf0 = np[0];
            pf1 = np[1];
        }

        // --- conv: acc[oc pair] += X[x+k-2][c] * w[k][c][oc], packed f32x2 ---
        unsigned long long a0 = 0, a1 = 0, a2 = 0, a3 = 0;
        const float* Xp = &Xs[p][0];
        for (int k = 0; k < Kn; ++k) {
            const float* xk = Xp + x + k;
            const ulonglong2* wk = ((const ulonglong2*)Wsm) + (size_t)k * Cn * 8 + (ocb >> 2);
#pragma unroll
            for (int c = 0; c < Cn; ++c) {
                float xv = xk[c * XW];
                unsigned long long xx;
                asm("mov.b64 %0, {%1, %1};" : "=l"(xx) : "r"(__float_as_uint(xv)));
                ulonglong2 wa = wk[c * 8];
                ulonglong2 wb = wk[c * 8 + 1];
                asm("fma.rn.f32x2 %0, %1, %2, %0;" : "+l"(a0) : "l"(xx), "l"(wa.x));
                asm("fma.rn.f32x2 %0, %1, %2, %0;" : "+l"(a1) : "l"(xx), "l"(wa.y));
                asm("fma.rn.f32x2 %0, %1, %2, %0;" : "+l"(a2) : "l"(xx), "l"(wb.x));
                asm("fma.rn.f32x2 %0, %1, %2, %0;" : "+l"(a3) : "l"(xx), "l"(wb.y));
            }
        }

        // --- epilogue: relu(acc + bias) ---
        float r[8];
        {
            unsigned lo, hi;
            asm("mov.b64 {%0,%1}, %2;" : "=r"(lo), "=r"(hi) : "l"(a0));
            r[0] = __uint_as_float(lo); r[1] = __uint_as_float(hi);
            asm("mov.b64 {%0,%1}, %2;" : "=r"(lo), "=r"(hi) : "l"(a1));
            r[2] = __uint_as_float(lo); r[3] = __uint_as_float(hi);
            asm("mov.b64 {%0,%1}, %2;" : "=r"(lo), "=r"(hi) : "l"(a2));
            r[4] = __uint_as_float(lo); r[5] = __uint_as_float(hi);
            asm("mov.b64 {%0,%1}, %2;" : "=r"(lo), "=r"(hi) : "l"(a3));
            r[6] = __uint_as_float(lo); r[7] = __uint_as_float(hi);
        }
#pragma unroll
        for (int j = 0; j < 8; ++j) r[j] = fmaxf(r[j] + bv[j], 0.f);

        // store output row
        float4* op = (float4*)(outb + (size_t)i * rstride + ocb);
        op[0] = make_float4(r[0], r[1], r[2], r[3]);
        op[1] = make_float4(r[4], r[5], r[6], r[7]);

        if (more) {
            // next state: X_{i+1} = r_i + input row i+1
            float xn[8];
            xn[0] = r[0] + pf0.x; xn[1] = r[1] + pf0.y;
            xn[2] = r[2] + pf0.z; xn[3] = r[3] + pf0.w;
            xn[4] = r[4] + pf1.x; xn[5] = r[5] + pf1.y;
            xn[6] = r[6] + pf1.z; xn[7] = r[7] + pf1.w;

            const int pn = p ^ 1;
            float* Xn = &Xs[pn][0];
#pragma unroll
            for (int j = 0; j < 8; ++j) Xn[(ocb + j) * XW + 2 + x] = xn[j];

            // halo to neighbors (our x 0,1 -> left's xi 34,35; our x 30,31 -> right's xi 0,1)
            if (x < 2 && rank > 0) {
#pragma unroll
                for (int j = 0; j < 8; ++j) {
                    unsigned ra = left_base +
                        ((unsigned)(pn * Cn * XW + (ocb + j) * XW + 34 + x) << 2);
                    asm volatile("st.shared::cluster.f32 [%0], %1;" :: "r"(ra), "f"(xn[j]) : "memory");
                }
            }
            if (x >= 30 && rank < 7) {
#pragma unroll
                for (int j = 0; j < 8; ++j) {
                    unsigned ra = right_base +
                        ((unsigned)(pn * Cn * XW + (ocb + j) * XW + (x - 30)) << 2);
                    asm volatile("st.shared::cluster.f32 [%0], %1;" :: "r"(ra), "f"(xn[j]) : "memory");
                }
            }
        }

        // cluster barrier: release our halo stores, acquire neighbors' (per-row sync)
        asm volatile("barrier.cluster.arrive.aligned;\n\tbarrier.cluster.wait.aligned;" ::: "memory");
    }
}

extern "C" void kernel_launch(void* const* d_in, const int* in_sizes, int n_in,
                              void* d_out, int out_size)
{
    const float* in   = (const float*)d_in[0];
    const float* w    = (const float*)d_in[1];
    const float* bias = (const float*)d_in[2];
    float* out        = (float*)d_out;
    (void)in_sizes; (void)n_in; (void)out_size;

    mvcnn_down_kernel<<<dim3(Bn * 8), dim3(128)>>>(in, w, bias, out);
}